// round 10
// baseline (speedup 1.0000x reference)
#include <cuda_runtime.h>
#include <cstdint>

#define BATCHN 4096
#define NI 784
#define WID 16000
#define NHID 4
#define NLAYERS 5                // input layer + 4 hidden
#define NCLS 10
#define W64 (BATCHN / 64)
#define NSLICE (BATCHN / 32)     // 128 CTA slices of 32 samples
#define GROUP (WID / NCLS)       // 1600 neurons per class
#define HGRP (GROUP / 2)         // 800 words per reduce warp
#define KWORDS (HGRP / 32)       // 25 words per lane
#define NW 25                    // inputs per warp in ballot-pack (32*25 >= 784)

// Device-resident state; referenced ONLY from device code.
__device__ uint32_t g_gidx[NLAYERS][WID];           // packed gate descriptors

static __device__ __forceinline__ uint32_t read_bool(const void* __restrict__ p,
                                                     size_t e, int mode) {
    if (mode == 1) return ((const uint32_t*)p)[e] != 0u;
    if (mode == 0) return ((const uint8_t*)p)[e] != 0u;
    return ((const uint16_t*)p)[e] != 0u;
}

// Decide bool encoding from 64 staged words of x (Bernoulli(0.5) data makes
// misclassification statistically impossible).
static __device__ __forceinline__ int mode_from_words(const uint32_t* w64v) {
    bool w32 = true, bf16 = true, u8 = true;
    for (int i = 0; i < 64; i++) {
        uint32_t w = w64v[i];
        if (!(w == 0u || w == 1u || w == 0x3F800000u)) w32 = false;
        uint32_t h0 = w & 0xFFFFu, h1 = w >> 16;
        if (!((h0 == 0u || h0 == 0x3F80u) && (h1 == 0u || h1 == 0x3F80u))) bf16 = false;
        if ((w & 0xFEFEFEFEu) != 0u) u8 = false;
    }
    return w32 ? 1 : (bf16 ? 2 : (u8 ? 0 : 1));
}

// ---------------------------------------------------------------------------
// prep_idx_k: pack (ia, ib, na, nb) -> one u32 per gate, all 5 layers.
// Per-block local mode detection (no cross-kernel g_mode dependency).
// ---------------------------------------------------------------------------
__global__ void prep_idx_k(const void* __restrict__ x,
                           const int* __restrict__ ia0, const int* __restrict__ ib0,
                           const void* __restrict__ ng0,
                           const int* __restrict__ iah, const int* __restrict__ ibh,
                           const void* __restrict__ ngh) {
    __shared__ int s_mode;
    if (threadIdx.x == 0) {
        uint32_t w[64];
        const uint32_t* xw = (const uint32_t*)x;
#pragma unroll
        for (int i = 0; i < 64; i++) w[i] = xw[i];
        s_mode = mode_from_words(w);
    }
    __syncthreads();
    int mode = s_mode;

    int t = blockIdx.x * blockDim.x + threadIdx.x;
    if (t >= NLAYERS * WID) return;
    int layer = t / WID;
    int n = t - layer * WID;
    uint32_t ia, ib, na, nb;
    if (layer == 0) {
        ia = (uint32_t)ia0[n];
        ib = (uint32_t)ib0[n];
        na = read_bool(ng0, 2 * (size_t)n, mode);
        nb = read_bool(ng0, 2 * (size_t)n + 1, mode);
    } else {
        int k = layer - 1;
        ia = (uint32_t)iah[(size_t)k * WID + n];
        ib = (uint32_t)ibh[(size_t)k * WID + n];
        na = read_bool(ngh, ((size_t)k * WID + n) * 2, mode);
        nb = read_bool(ngh, ((size_t)k * WID + n) * 2 + 1, mode);
    }
    g_gidx[layer][n] = ia | (ib << 14) | (na << 28) | (nb << 29);
}

// ---------------------------------------------------------------------------
// fused_k: CTA = one 32-sample batch slice.
//   1. ballot-transpose the CTA's 32 x 784 bool inputs into xp[] (smem)
//   2. 5 logic layers with smem-resident activations (LDS gathers)
//   3. in-CTA GroupSum (CSA bit-planes + ballots), direct stores to out
// Zero intermediate gmem traffic.
// ---------------------------------------------------------------------------
#define SM_BUF 16384
#define SM_WORDS (2 * SM_BUF + NI)
#define SM_BYTES (SM_WORDS * 4)

__global__ void __launch_bounds__(1024) fused_k(const void* __restrict__ x,
                                                float* __restrict__ out) {
    extern __shared__ uint32_t sm[];
    uint32_t* h0 = sm;
    uint32_t* h1 = sm + SM_BUF;
    uint32_t* xp = sm + 2 * SM_BUF;
    __shared__ int partial[NCLS][2][32];
    __shared__ int s_mode;

    int s = blockIdx.x;              // slice: samples [32s, 32s+32)
    int t = threadIdx.x;
    int wid = t >> 5;
    int lane = t & 31;

    // --- mode detection: stage 64 words of x, thread 0 classifies ---
    if (t < 64) xp[t] = ((const uint32_t*)x)[t];
    __syncthreads();
    if (t == 0) s_mode = mode_from_words(xp);
    __syncthreads();
    int mode = s_mode;

    // --- ballot-transpose input pack: xp[i] bit j = sample 32s+j ---
    // Warp wid handles inputs [wid*NW, wid*NW+NW); lane j streams row 32s+j.
    {
        size_t rowbase = (size_t)(32 * s + lane) * NI;
        int i0 = wid * NW;
#pragma unroll 5
        for (int m = 0; m < NW; m++) {
            int i = i0 + m;
            uint32_t v = (i < NI) ? read_bool(x, rowbase + i, mode) : 0u;
            uint32_t mask = __ballot_sync(0xFFFFFFFFu, v);
            if (lane == 0 && i < NI) xp[i] = mask;
        }
    }
    __syncthreads();

    // --- Layer 0: xp -> h0 ---
    {
        const uint32_t* __restrict__ gl = g_gidx[0];
#pragma unroll 4
        for (int g = t; g < WID; g += 1024) {
            uint32_t d = gl[g];
            uint32_t a = xp[d & 0x3FFFu];
            uint32_t b = xp[(d >> 14) & 0x3FFFu];
            h0[g] = (a ^ (0u - ((d >> 28) & 1u))) & (b ^ (0u - ((d >> 29) & 1u)));
        }
    }
    __syncthreads();

    // --- Hidden layers 1..4: h0->h1->h0->h1->h0 ---
#pragma unroll
    for (int L = 1; L < NLAYERS; L++) {
        const uint32_t* __restrict__ hs = ((L & 1) == 1) ? h0 : h1;
        uint32_t* __restrict__ hd = ((L & 1) == 1) ? h1 : h0;
        const uint32_t* __restrict__ gl = g_gidx[L];
#pragma unroll 4
        for (int g = t; g < WID; g += 1024) {
            uint32_t d = gl[g];
            uint32_t a = hs[d & 0x3FFFu];
            uint32_t b = hs[(d >> 14) & 0x3FFFu];
            hd[g] = (a ^ (0u - ((d >> 28) & 1u))) & (b ^ (0u - ((d >> 29) & 1u)));
        }
        __syncthreads();
    }

    // --- In-CTA GroupSum from h0. 20 warps: warp = (class c, half hf). ---
    if (wid < 2 * NCLS) {
        int c = wid >> 1;
        int hf = wid & 1;
        const uint32_t* __restrict__ p = h0 + c * GROUP + hf * HGRP + lane;
        uint32_t s0 = 0, s1 = 0, s2 = 0, s3 = 0, s4 = 0;
#pragma unroll
        for (int k = 0; k < KWORDS; k++) {       // 25 stride-1 LDS words
            uint32_t cc = p[k * 32];
            uint32_t tt;
            tt = s0 & cc; s0 ^= cc; cc = tt;
            tt = s1 & cc; s1 ^= cc; cc = tt;
            tt = s2 & cc; s2 ^= cc; cc = tt;
            tt = s3 & cc; s3 ^= cc; cc = tt;
            s4 ^= cc;                             // counts <= 25 < 32
        }
#pragma unroll
        for (int b = 0; b < 32; b++) {
            int tot = __popc(__ballot_sync(0xFFFFFFFFu, (s0 >> b) & 1u))
                    + 2  * __popc(__ballot_sync(0xFFFFFFFFu, (s1 >> b) & 1u))
                    + 4  * __popc(__ballot_sync(0xFFFFFFFFu, (s2 >> b) & 1u))
                    + 8  * __popc(__ballot_sync(0xFFFFFFFFu, (s3 >> b) & 1u))
                    + 16 * __popc(__ballot_sync(0xFFFFFFFFu, (s4 >> b) & 1u));
            if (lane == b) partial[c][hf][b] = tot;
        }
    }
    __syncthreads();

    // --- 320 threads: combine halves, store exactly once. ---
    if (t < NCLS * 32) {
        int c = t >> 5;
        int b = t & 31;
        out[(size_t)(s * 32 + b) * NCLS + c] =
            (float)(partial[c][0][b] + partial[c][1][b]);
    }
}

// ---------------------------------------------------------------------------
// Bind inputs BY ELEMENT COUNT (robust to metadata ordering).
// Output: float32 [BATCH, NCLS]
// ---------------------------------------------------------------------------
extern "C" void kernel_launch(void* const* d_in, const int* in_sizes, int n_in,
                              void* d_out, int out_size) {
    const void* x = nullptr;
    const int *ia0 = nullptr, *ib0 = nullptr, *iah = nullptr, *ibh = nullptr;
    const void *ng0 = nullptr, *ngh = nullptr;

    for (int i = 0; i < n_in; i++) {
        int sz = in_sizes[i];
        if (sz == BATCHN * NI) {
            x = d_in[i];
        } else if (sz == WID) {
            if (!ia0) ia0 = (const int*)d_in[i]; else ib0 = (const int*)d_in[i];
        } else if (sz == WID * 2) {
            ng0 = d_in[i];
        } else if (sz == NHID * WID) {
            if (!iah) iah = (const int*)d_in[i]; else ibh = (const int*)d_in[i];
        } else if (sz == NHID * WID * 2) {
            ngh = d_in[i];
        }
    }
    float* out = (float*)d_out;

    static bool attr_set = false;
    if (!attr_set) {
        cudaFuncSetAttribute(fused_k, cudaFuncAttributeMaxDynamicSharedMemorySize,
                             SM_BYTES);
        attr_set = true;
    }

    prep_idx_k<<<(NLAYERS * WID + 255) / 256, 256>>>(x, ia0, ib0, ng0, iah, ibh, ngh);

    fused_k<<<NSLICE, 1024, SM_BYTES>>>(x, out);
}

// round 11
// speedup vs baseline: 1.2039x; 1.2039x over previous
#include <cuda_runtime.h>
#include <cstdint>

#define BATCHN 4096
#define NI 784
#define NIP 800                  // padded row stride for stg (bytes)
#define WID 16000
#define NHID 4
#define NLAYERS 5                // input layer + 4 hidden
#define NCLS 10
#define NSLICE (BATCHN / 32)     // 128 CTA slices of 32 samples
#define GROUP (WID / NCLS)       // 1600 neurons per class
#define HGRP (GROUP / 2)         // 800 words per reduce warp
#define KWORDS (HGRP / 32)       // 25 words per lane

// Device-resident state; referenced ONLY from device code.
__device__ uint32_t g_gidx[NLAYERS][WID];           // packed gate descriptors

static __device__ __forceinline__ uint32_t read_bool(const void* __restrict__ p,
                                                     size_t e, int mode) {
    if (mode == 1) return ((const uint32_t*)p)[e] != 0u;
    if (mode == 0) return ((const uint8_t*)p)[e] != 0u;
    return ((const uint16_t*)p)[e] != 0u;
}

// Decide bool encoding from 64 staged words of x (Bernoulli(0.5) data makes
// misclassification statistically impossible).
static __device__ __forceinline__ int mode_from_words(const uint32_t* w64v) {
    bool w32 = true, bf16 = true, u8 = true;
    for (int i = 0; i < 64; i++) {
        uint32_t w = w64v[i];
        if (!(w == 0u || w == 1u || w == 0x3F800000u)) w32 = false;
        uint32_t h0 = w & 0xFFFFu, h1 = w >> 16;
        if (!((h0 == 0u || h0 == 0x3F80u) && (h1 == 0u || h1 == 0x3F80u))) bf16 = false;
        if ((w & 0xFEFEFEFEu) != 0u) u8 = false;
    }
    return w32 ? 1 : (bf16 ? 2 : (u8 ? 0 : 1));
}

// ---------------------------------------------------------------------------
// prep_idx_k: pack (ia, ib, na, nb) -> one u32 per gate, all 5 layers.
// Per-block local mode detection (no cross-kernel dependency).
// ---------------------------------------------------------------------------
__global__ void prep_idx_k(const void* __restrict__ x,
                           const int* __restrict__ ia0, const int* __restrict__ ib0,
                           const void* __restrict__ ng0,
                           const int* __restrict__ iah, const int* __restrict__ ibh,
                           const void* __restrict__ ngh) {
    __shared__ int s_mode;
    if (threadIdx.x == 0) {
        uint32_t w[64];
        const uint32_t* xw = (const uint32_t*)x;
#pragma unroll
        for (int i = 0; i < 64; i++) w[i] = xw[i];
        s_mode = mode_from_words(w);
    }
    __syncthreads();
    int mode = s_mode;

    int t = blockIdx.x * blockDim.x + threadIdx.x;
    if (t >= NLAYERS * WID) return;
    int layer = t / WID;
    int n = t - layer * WID;
    uint32_t ia, ib, na, nb;
    if (layer == 0) {
        ia = (uint32_t)ia0[n];
        ib = (uint32_t)ib0[n];
        na = read_bool(ng0, 2 * (size_t)n, mode);
        nb = read_bool(ng0, 2 * (size_t)n + 1, mode);
    } else {
        int k = layer - 1;
        ia = (uint32_t)iah[(size_t)k * WID + n];
        ib = (uint32_t)ibh[(size_t)k * WID + n];
        na = read_bool(ngh, ((size_t)k * WID + n) * 2, mode);
        nb = read_bool(ngh, ((size_t)k * WID + n) * 2 + 1, mode);
    }
    g_gidx[layer][n] = ia | (ib << 14) | (na << 28) | (nb << 29);
}

// ---------------------------------------------------------------------------
// fused_k: CTA = one 32-sample batch slice.
//   Phase A: COALESCED load of the slice's 32 bool rows into smem bytes
//            (warp = row, lanes stride the row).
//   Phase B: byte-transpose -> xp[i] (bit j = sample 32s+j). Conflict-free.
//   Then: 5 logic layers with smem-resident activations (LDS gathers),
//   and in-CTA GroupSum (CSA bit-planes + ballots) stored straight to out.
// stg aliases h1 (h1 is first written in layer 1). No intermediate gmem.
// ---------------------------------------------------------------------------
#define SM_BUF 16384
#define SM_WORDS (2 * SM_BUF + NI)
#define SM_BYTES (SM_WORDS * 4)

__global__ void __launch_bounds__(1024) fused_k(const void* __restrict__ x,
                                                float* __restrict__ out) {
    extern __shared__ uint32_t sm[];
    uint32_t* h0 = sm;
    uint32_t* h1 = sm + SM_BUF;
    uint32_t* xp = sm + 2 * SM_BUF;
    uint8_t*  stg = (uint8_t*)h1;           // 32 x NIP bytes, dies before L=1
    __shared__ int partial[NCLS][2][32];
    __shared__ int s_mode;

    int s = blockIdx.x;              // slice: samples [32s, 32s+32)
    int t = threadIdx.x;
    int wid = t >> 5;
    int lane = t & 31;

    // --- mode detection: stage 64 words of x, thread 0 classifies ---
    if (t < 64) xp[t] = ((const uint32_t*)x)[t];
    __syncthreads();
    if (t == 0) s_mode = mode_from_words(xp);
    __syncthreads();
    int mode = s_mode;

    // --- Phase A: coalesced row loads. warp = sample row, lanes stride. ---
    {
        size_t rowbase = (size_t)(32 * s + wid) * NI;
        uint8_t* rowdst = stg + wid * NIP;
        for (int i = lane; i < NI; i += 32)
            rowdst[i] = (uint8_t)read_bool(x, rowbase + i, mode);
    }
    __syncthreads();

    // --- Phase B: transpose bytes -> packed words xp[i]. ---
    if (t < NI) {
        uint32_t acc = 0;
#pragma unroll
        for (int j = 0; j < 32; j++)
            acc |= (uint32_t)stg[j * NIP + t] << j;
        xp[t] = acc;
    }
    __syncthreads();

    // --- Layer 0: xp -> h0 ---
    {
        const uint32_t* __restrict__ gl = g_gidx[0];
#pragma unroll 4
        for (int g = t; g < WID; g += 1024) {
            uint32_t d = gl[g];
            uint32_t a = xp[d & 0x3FFFu];
            uint32_t b = xp[(d >> 14) & 0x3FFFu];
            h0[g] = (a ^ (0u - ((d >> 28) & 1u))) & (b ^ (0u - ((d >> 29) & 1u)));
        }
    }
    __syncthreads();

    // --- Hidden layers 1..4: h0->h1->h0->h1->h0 ---
#pragma unroll
    for (int L = 1; L < NLAYERS; L++) {
        const uint32_t* __restrict__ hs = ((L & 1) == 1) ? h0 : h1;
        uint32_t* __restrict__ hd = ((L & 1) == 1) ? h1 : h0;
        const uint32_t* __restrict__ gl = g_gidx[L];
#pragma unroll 4
        for (int g = t; g < WID; g += 1024) {
            uint32_t d = gl[g];
            uint32_t a = hs[d & 0x3FFFu];
            uint32_t b = hs[(d >> 14) & 0x3FFFu];
            hd[g] = (a ^ (0u - ((d >> 28) & 1u))) & (b ^ (0u - ((d >> 29) & 1u)));
        }
        __syncthreads();
    }

    // --- In-CTA GroupSum from h0. 20 warps: warp = (class c, half hf). ---
    if (wid < 2 * NCLS) {
        int c = wid >> 1;
        int hf = wid & 1;
        const uint32_t* __restrict__ p = h0 + c * GROUP + hf * HGRP + lane;
        uint32_t s0 = 0, s1 = 0, s2 = 0, s3 = 0, s4 = 0;
#pragma unroll
        for (int k = 0; k < KWORDS; k++) {       // 25 stride-1 LDS words
            uint32_t cc = p[k * 32];
            uint32_t tt;
            tt = s0 & cc; s0 ^= cc; cc = tt;
            tt = s1 & cc; s1 ^= cc; cc = tt;
            tt = s2 & cc; s2 ^= cc; cc = tt;
            tt = s3 & cc; s3 ^= cc; cc = tt;
            s4 ^= cc;                             // counts <= 25 < 32
        }
#pragma unroll
        for (int b = 0; b < 32; b++) {
            int tot = __popc(__ballot_sync(0xFFFFFFFFu, (s0 >> b) & 1u))
                    + 2  * __popc(__ballot_sync(0xFFFFFFFFu, (s1 >> b) & 1u))
                    + 4  * __popc(__ballot_sync(0xFFFFFFFFu, (s2 >> b) & 1u))
                    + 8  * __popc(__ballot_sync(0xFFFFFFFFu, (s3 >> b) & 1u))
                    + 16 * __popc(__ballot_sync(0xFFFFFFFFu, (s4 >> b) & 1u));
            if (lane == b) partial[c][hf][b] = tot;
        }
    }
    __syncthreads();

    // --- 320 threads: combine halves, store exactly once. ---
    if (t < NCLS * 32) {
        int c = t >> 5;
        int b = t & 31;
        out[(size_t)(s * 32 + b) * NCLS + c] =
            (float)(partial[c][0][b] + partial[c][1][b]);
    }
}

// ---------------------------------------------------------------------------
// Bind inputs BY ELEMENT COUNT (robust to metadata ordering).
// Output: float32 [BATCH, NCLS]
// ---------------------------------------------------------------------------
extern "C" void kernel_launch(void* const* d_in, const int* in_sizes, int n_in,
                              void* d_out, int out_size) {
    const void* x = nullptr;
    const int *ia0 = nullptr, *ib0 = nullptr, *iah = nullptr, *ibh = nullptr;
    const void *ng0 = nullptr, *ngh = nullptr;

    for (int i = 0; i < n_in; i++) {
        int sz = in_sizes[i];
        if (sz == BATCHN * NI) {
            x = d_in[i];
        } else if (sz == WID) {
            if (!ia0) ia0 = (const int*)d_in[i]; else ib0 = (const int*)d_in[i];
        } else if (sz == WID * 2) {
            ng0 = d_in[i];
        } else if (sz == NHID * WID) {
            if (!iah) iah = (const int*)d_in[i]; else ibh = (const int*)d_in[i];
        } else if (sz == NHID * WID * 2) {
            ngh = d_in[i];
        }
    }
    float* out = (float*)d_out;

    static bool attr_set = false;
    if (!attr_set) {
        cudaFuncSetAttribute(fused_k, cudaFuncAttributeMaxDynamicSharedMemorySize,
                             SM_BYTES);
        attr_set = true;
    }

    prep_idx_k<<<(NLAYERS * WID + 255) / 256, 256>>>(x, ia0, ib0, ng0, iah, ibh, ngh);

    fused_k<<<NSLICE, 1024, SM_BYTES>>>(x, out);
}

// round 12
// speedup vs baseline: 1.2898x; 1.0714x over previous
#include <cuda_runtime.h>
#include <cstdint>

#define BATCHN 4096
#define NI 784
#define NIP 800                  // padded row stride for stg (bytes)
#define WID 16000
#define NG4 (WID / 4)            // 4000 uint4 descriptors per layer
#define NHID 4
#define NLAYERS 5                // input layer + 4 hidden
#define NCLS 10
#define NSLICE (BATCHN / 32)     // 128 CTA slices of 32 samples
#define GROUP (WID / NCLS)       // 1600 neurons per class
#define HGRP (GROUP / 2)         // 800 words per reduce warp
#define KWORDS (HGRP / 32)       // 25 words per lane

// Device-resident state; referenced ONLY from device code.
// Descriptor: ia | ib<<14 | na<<31 | nb<<30
__device__ uint32_t g_gidx[NLAYERS][WID];

static __device__ __forceinline__ uint32_t read_bool(const void* __restrict__ p,
                                                     size_t e, int mode) {
    if (mode == 1) return ((const uint32_t*)p)[e] != 0u;
    if (mode == 0) return ((const uint8_t*)p)[e] != 0u;
    return ((const uint16_t*)p)[e] != 0u;
}

static __device__ __forceinline__ int mode_from_words(const uint32_t* w64v) {
    bool w32 = true, bf16 = true, u8 = true;
    for (int i = 0; i < 64; i++) {
        uint32_t w = w64v[i];
        if (!(w == 0u || w == 1u || w == 0x3F800000u)) w32 = false;
        uint32_t h0 = w & 0xFFFFu, h1 = w >> 16;
        if (!((h0 == 0u || h0 == 0x3F80u) && (h1 == 0u || h1 == 0x3F80u))) bf16 = false;
        if ((w & 0xFEFEFEFEu) != 0u) u8 = false;
    }
    return w32 ? 1 : (bf16 ? 2 : (u8 ? 0 : 1));
}

// ---------------------------------------------------------------------------
// prep_idx_k: pack (ia, ib, na, nb) -> one u32 per gate.
// na in bit 31, nb in bit 30 (1-op sign-extend mask extraction downstream).
// ---------------------------------------------------------------------------
__global__ void prep_idx_k(const void* __restrict__ x,
                           const int* __restrict__ ia0, const int* __restrict__ ib0,
                           const void* __restrict__ ng0,
                           const int* __restrict__ iah, const int* __restrict__ ibh,
                           const void* __restrict__ ngh) {
    __shared__ int s_mode;
    if (threadIdx.x == 0) {
        uint32_t w[64];
        const uint32_t* xw = (const uint32_t*)x;
#pragma unroll
        for (int i = 0; i < 64; i++) w[i] = xw[i];
        s_mode = mode_from_words(w);
    }
    __syncthreads();
    int mode = s_mode;

    int t = blockIdx.x * blockDim.x + threadIdx.x;
    if (t >= NLAYERS * WID) return;
    int layer = t / WID;
    int n = t - layer * WID;
    uint32_t ia, ib, na, nb;
    if (layer == 0) {
        ia = (uint32_t)ia0[n];
        ib = (uint32_t)ib0[n];
        na = read_bool(ng0, 2 * (size_t)n, mode);
        nb = read_bool(ng0, 2 * (size_t)n + 1, mode);
    } else {
        int k = layer - 1;
        ia = (uint32_t)iah[(size_t)k * WID + n];
        ib = (uint32_t)ibh[(size_t)k * WID + n];
        na = read_bool(ngh, ((size_t)k * WID + n) * 2, mode);
        nb = read_bool(ngh, ((size_t)k * WID + n) * 2 + 1, mode);
    }
    g_gidx[layer][n] = ia | (ib << 14) | (na << 31) | (nb << 30);
}

// ---------------------------------------------------------------------------
// Gate: (a ^ ma) & (b ^ mb); ma from bit 31, mb from bit 30 (sign-extends).
// ---------------------------------------------------------------------------
static __device__ __forceinline__ uint32_t gate(uint32_t d,
                                                const uint32_t* __restrict__ hs) {
    uint32_t a = hs[d & 0x3FFFu];
    uint32_t b = hs[(d >> 14) & 0x3FFFu];
    uint32_t ma = (uint32_t)(((int32_t)d) >> 31);
    uint32_t mb = (uint32_t)(((int32_t)(d << 1)) >> 31);
    return (a ^ ma) & (b ^ mb);
}

// One layer: thread t -> gates 4p..4p+3 for p = c*1024+t, c = 0..3.
// uint4 descriptor loads (coalesced LDG.128), STS.128 stores, 8-way LDS MLP.
static __device__ __forceinline__ void run_layer(const uint4* __restrict__ gl4,
                                                 const uint32_t* __restrict__ hs,
                                                 uint4* __restrict__ hd4, int t) {
    bool has3 = (3072 + t) < NG4;            // t < 928
    uint4 d0 = gl4[t];
    uint4 d1 = gl4[1024 + t];
    uint4 d2 = gl4[2048 + t];
    uint4 d3 = has3 ? gl4[3072 + t] : make_uint4(0u, 0u, 0u, 0u);

    uint4 r;
    r.x = gate(d0.x, hs); r.y = gate(d0.y, hs);
    r.z = gate(d0.z, hs); r.w = gate(d0.w, hs);
    hd4[t] = r;
    r.x = gate(d1.x, hs); r.y = gate(d1.y, hs);
    r.z = gate(d1.z, hs); r.w = gate(d1.w, hs);
    hd4[1024 + t] = r;
    r.x = gate(d2.x, hs); r.y = gate(d2.y, hs);
    r.z = gate(d2.z, hs); r.w = gate(d2.w, hs);
    hd4[2048 + t] = r;
    if (has3) {
        r.x = gate(d3.x, hs); r.y = gate(d3.y, hs);
        r.z = gate(d3.z, hs); r.w = gate(d3.w, hs);
        hd4[3072 + t] = r;
    }
}

// ---------------------------------------------------------------------------
// fused_k: CTA = one 32-sample batch slice. Coalesced pack -> 5 smem-resident
// logic layers (vectorized) -> in-CTA GroupSum -> direct stores.
// ---------------------------------------------------------------------------
#define SM_BUF 16384
#define SM_WORDS (2 * SM_BUF + NI)
#define SM_BYTES (SM_WORDS * 4)

__global__ void __launch_bounds__(1024) fused_k(const void* __restrict__ x,
                                                float* __restrict__ out) {
    extern __shared__ uint32_t sm[];
    uint32_t* h0 = sm;
    uint32_t* h1 = sm + SM_BUF;
    uint32_t* xp = sm + 2 * SM_BUF;
    uint8_t*  stg = (uint8_t*)h1;           // 32 x NIP bytes, dies before L=1
    __shared__ int partial[NCLS][2][32];
    __shared__ int s_mode;

    int s = blockIdx.x;              // slice: samples [32s, 32s+32)
    int t = threadIdx.x;
    int wid = t >> 5;
    int lane = t & 31;

    // --- mode detection ---
    if (t < 64) xp[t] = ((const uint32_t*)x)[t];
    __syncthreads();
    if (t == 0) s_mode = mode_from_words(xp);
    __syncthreads();
    int mode = s_mode;

    // --- Phase A: coalesced row loads. warp = sample row, lanes stride. ---
    {
        size_t rowbase = (size_t)(32 * s + wid) * NI;
        uint8_t* rowdst = stg + wid * NIP;
        for (int i = lane; i < NI; i += 32)
            rowdst[i] = (uint8_t)read_bool(x, rowbase + i, mode);
    }
    __syncthreads();

    // --- Phase B: transpose bytes -> packed words xp[i]. ---
    if (t < NI) {
        uint32_t acc = 0;
#pragma unroll
        for (int j = 0; j < 32; j++)
            acc |= (uint32_t)stg[j * NIP + t] << j;
        xp[t] = acc;
    }
    __syncthreads();

    // --- Layer 0: xp -> h0 ---
    run_layer((const uint4*)g_gidx[0], xp, (uint4*)h0, t);
    __syncthreads();

    // --- Hidden layers 1..4: h0->h1->h0->h1->h0 ---
    run_layer((const uint4*)g_gidx[1], h0, (uint4*)h1, t);
    __syncthreads();
    run_layer((const uint4*)g_gidx[2], h1, (uint4*)h0, t);
    __syncthreads();
    run_layer((const uint4*)g_gidx[3], h0, (uint4*)h1, t);
    __syncthreads();
    run_layer((const uint4*)g_gidx[4], h1, (uint4*)h0, t);
    __syncthreads();

    // --- In-CTA GroupSum from h0. 20 warps: warp = (class c, half hf). ---
    if (wid < 2 * NCLS) {
        int c = wid >> 1;
        int hf = wid & 1;
        const uint32_t* __restrict__ p = h0 + c * GROUP + hf * HGRP + lane;
        uint32_t s0 = 0, s1 = 0, s2 = 0, s3 = 0, s4 = 0;
#pragma unroll
        for (int k = 0; k < KWORDS; k++) {       // 25 stride-1 LDS words
            uint32_t cc = p[k * 32];
            uint32_t tt;
            tt = s0 & cc; s0 ^= cc; cc = tt;
            tt = s1 & cc; s1 ^= cc; cc = tt;
            tt = s2 & cc; s2 ^= cc; cc = tt;
            tt = s3 & cc; s3 ^= cc; cc = tt;
            s4 ^= cc;                             // counts <= 25 < 32
        }
#pragma unroll
        for (int b = 0; b < 32; b++) {
            int tot = __popc(__ballot_sync(0xFFFFFFFFu, (s0 >> b) & 1u))
                    + 2  * __popc(__ballot_sync(0xFFFFFFFFu, (s1 >> b) & 1u))
                    + 4  * __popc(__ballot_sync(0xFFFFFFFFu, (s2 >> b) & 1u))
                    + 8  * __popc(__ballot_sync(0xFFFFFFFFu, (s3 >> b) & 1u))
                    + 16 * __popc(__ballot_sync(0xFFFFFFFFu, (s4 >> b) & 1u));
            if (lane == b) partial[c][hf][b] = tot;
        }
    }
    __syncthreads();

    // --- 320 threads: combine halves, store exactly once. ---
    if (t < NCLS * 32) {
        int c = t >> 5;
        int b = t & 31;
        out[(size_t)(s * 32 + b) * NCLS + c] =
            (float)(partial[c][0][b] + partial[c][1][b]);
    }
}

// ---------------------------------------------------------------------------
// Bind inputs BY ELEMENT COUNT. Output: float32 [BATCH, NCLS]
// ---------------------------------------------------------------------------
extern "C" void kernel_launch(void* const* d_in, const int* in_sizes, int n_in,
                              void* d_out, int out_size) {
    const void* x = nullptr;
    const int *ia0 = nullptr, *ib0 = nullptr, *iah = nullptr, *ibh = nullptr;
    const void *ng0 = nullptr, *ngh = nullptr;

    for (int i = 0; i < n_in; i++) {
        int sz = in_sizes[i];
        if (sz == BATCHN * NI) {
            x = d_in[i];
        } else if (sz == WID) {
            if (!ia0) ia0 = (const int*)d_in[i]; else ib0 = (const int*)d_in[i];
        } else if (sz == WID * 2) {
            ng0 = d_in[i];
        } else if (sz == NHID * WID) {
            if (!iah) iah = (const int*)d_in[i]; else ibh = (const int*)d_in[i];
        } else if (sz == NHID * WID * 2) {
            ngh = d_in[i];
        }
    }
    float* out = (float*)d_out;

    static bool attr_set = false;
    if (!attr_set) {
        cudaFuncSetAttribute(fused_k, cudaFuncAttributeMaxDynamicSharedMemorySize,
                             SM_BYTES);
        attr_set = true;
    }

    prep_idx_k<<<(NLAYERS * WID + 255) / 256, 256>>>(x, ia0, ib0, ng0, iah, ibh, ngh);

    fused_k<<<NSLICE, 1024, SM_BYTES>>>(x, out);
}